// round 11
// baseline (speedup 1.0000x reference)
#include <cuda_runtime.h>
#include <math.h>

#define B     64
#define T     256
#define DIM   1024
#define EMB   256
#define VOCAB 256
#define G4    4096   // 4*DIM
#define NCTA  128
#define NTHR  256
#define K_CH  128    // k elements per smem chunk
#define APITCH 136   // A_s row pitch (mod 32 == 8 -> conflict-free LDS.64)
#define CHF   (64*APITCH)  // floats per A chunk buffer

#define LOGITS_N (B*T*VOCAB)     // 4194304
#define HC_N     (2*B*DIM)       // 131072

// ---------------- device scratch ---------------------------------------------
__device__ float g_Wih0[G4*EMB];          //  4 MB
__device__ float g_Whh0[G4*DIM];          // 16.8 MB
__device__ float g_xg  [(size_t)T*B*G4];  // 268 MB (reused by both layers)
__device__ float g_hs0 [(size_t)T*B*DIM]; // 67 MB, layout [t][b][d]
__device__ float g_hs1 [(size_t)T*B*DIM]; // 67 MB
__device__ float g_cfin[2][B*DIM];
__device__ float g_hex [2][B*DIM];        // tf32-rounded, k-permuted h exchange
__device__ volatile unsigned g_flags[NCTA];  // per-CTA barrier flags (distinct addrs)

// ---------------- helpers ----------------------------------------------------
__device__ __forceinline__ unsigned f2tf32(float x){
    unsigned u; asm("cvt.rna.tf32.f32 %0, %1;" : "=r"(u) : "f"(x)); return u;
}
// within each k-octet, store order pairs (k, k+4): pos(i) = i<4 ? 2i : 2(i-4)+1
__device__ __forceinline__ int spf(int i){ return (i < 4) ? 2*i : 2*(i-4)+1; }

__device__ __forceinline__ void mma_tf32(float* c, const unsigned* a, const unsigned* b){
    asm volatile("mma.sync.aligned.m16n8k8.row.col.f32.tf32.tf32.f32 "
        "{%0,%1,%2,%3}, {%4,%5,%6,%7}, {%8,%9}, {%0,%1,%2,%3};\n"
        : "+f"(c[0]), "+f"(c[1]), "+f"(c[2]), "+f"(c[3])
        : "r"(a[0]), "r"(a[1]), "r"(a[2]), "r"(a[3]), "r"(b[0]), "r"(b[1]));
}

// Flag-array grid barrier: each CTA writes its own flag (distinct address),
// threads 0..NCTA-1 each poll one CTA's flag in parallel. No serialized atomics.
__device__ __forceinline__ void flag_barrier(unsigned target){
    __syncthreads();
    if (threadIdx.x == 0){
        __threadfence();                       // release this CTA's writes
        g_flags[blockIdx.x] = target;
    }
    if (threadIdx.x < NCTA){
        while (g_flags[threadIdx.x] < target) { }
    }
    __threadfence();                           // acquire
    __syncthreads();
}

// ---------------- weight norm ------------------------------------------------
__global__ void wnorm_kernel(const float* __restrict__ v,
                             const float* __restrict__ g, int mode)
{
    const int K = mode ? DIM : EMB;
    float* W = mode ? g_Whh0 : g_Wih0;
    int row = blockIdx.x;
    __shared__ float red[256];
    float s = 0.f;
    for (int i = threadIdx.x; i < K; i += 256) {
        float x = v[(size_t)row*K + i];
        s += x*x;
    }
    red[threadIdx.x] = s;
    __syncthreads();
    for (int o = 128; o > 0; o >>= 1) {
        if (threadIdx.x < o) red[threadIdx.x] += red[threadIdx.x + o];
        __syncthreads();
    }
    float scale = g[row] / sqrtf(red[0]);
    for (int i = threadIdx.x; i < K; i += 256)
        W[(size_t)row*K + i] = v[(size_t)row*K + i] * scale;
}

// ---------------- fp32 SIMT GEMM (input-side gates + logits) ----------------
__global__ __launch_bounds__(256, 2)
void gemm128_kernel(int mode,
                    const float* __restrict__ Aext,
                    const float* __restrict__ Bext,
                    float* __restrict__ Cext,
                    const float* __restrict__ bias1,
                    const float* __restrict__ bias2,
                    const int* __restrict__ xidx,
                    int N, int K)
{
    const float* A  = (mode == 0) ? Aext : (mode == 1 ? g_hs0 : g_hs1);
    const float* Bm = (mode == 0) ? g_Wih0 : Bext;
    float* C        = (mode == 2) ? Cext : g_xg;

    __shared__ float As[8][128];
    __shared__ float Bs[8][128];

    int tid = threadIdx.x;
    int tx = tid & 15, ty = tid >> 4;
    int m0 = blockIdx.y * 128, n0 = blockIdx.x * 128;

    int lrow = tid >> 1;
    int kq   = (tid & 1) * 4;

    int m = m0 + lrow;
    const float* arow;
    if (mode == 0) {
        int b = m & 63, t = m >> 6;
        arow = A + (size_t)xidx[b*T + t] * K;
    } else {
        arow = A + (size_t)m * K;
    }
    const float* brow = Bm + (size_t)(n0 + lrow) * K;

    float acc[8][8];
#pragma unroll
    for (int i = 0; i < 8; i++)
#pragma unroll
        for (int j = 0; j < 8; j++) acc[i][j] = 0.f;

    for (int kc = 0; kc < K; kc += 8) {
        float4 av = *(const float4*)(arow + kc + kq);
        float4 bv = *(const float4*)(brow + kc + kq);
        __syncthreads();
        As[kq+0][lrow] = av.x; As[kq+1][lrow] = av.y;
        As[kq+2][lrow] = av.z; As[kq+3][lrow] = av.w;
        Bs[kq+0][lrow] = bv.x; Bs[kq+1][lrow] = bv.y;
        Bs[kq+2][lrow] = bv.z; Bs[kq+3][lrow] = bv.w;
        __syncthreads();
#pragma unroll
        for (int k = 0; k < 8; k++) {
            float a[8], bb[8];
            *(float4*)&a[0]  = *(const float4*)&As[k][ty*8];
            *(float4*)&a[4]  = *(const float4*)&As[k][ty*8 + 4];
            *(float4*)&bb[0] = *(const float4*)&Bs[k][tx*8];
            *(float4*)&bb[4] = *(const float4*)&Bs[k][tx*8 + 4];
#pragma unroll
            for (int i = 0; i < 8; i++)
#pragma unroll
                for (int j = 0; j < 8; j++)
                    acc[i][j] += a[i] * bb[j];
        }
    }

#pragma unroll
    for (int i = 0; i < 8; i++) {
        int mm = m0 + ty*8 + i;
#pragma unroll
        for (int j = 0; j < 8; j++) {
            int nn = n0 + tx*8 + j;
            float v = acc[i][j] + bias1[nn] + (bias2 ? bias2[nn] : 0.f);
            if (mode == 2) {
                int b = mm & 63, t = mm >> 6;
                C[(size_t)b*(T*VOCAB) + (size_t)t*VOCAB + nn] = v;
            } else {
                C[(size_t)mm*N + nn] = v;
            }
        }
    }
}

// ---------------- persistent tf32 mma recurrence kernel ----------------------
// 128 CTAs x 256 threads (8 warps). CTA j owns dims [8j, 8j+8): 32 gate rows.
// Warp grid 4(m) x 2(n): warp tile m16 x n16. K chunked by 128 into smem,
// double-buffered cp.async, ONE __syncthreads per chunk, flag-array barrier.
__device__ __forceinline__ void load_chunk(const float* hsrc, int kcc, float* Abuf, int tid){
#pragma unroll
    for (int i = 0; i < 8; i++){
        int idx = tid + i*NTHR;          // 0..2047  (64 rows x 32 float4)
        int b = idx >> 5, q = idx & 31;
        const float* gp = hsrc + b*DIM + kcc*K_CH + q*4;
        unsigned sa = (unsigned)__cvta_generic_to_shared(Abuf + b*APITCH + q*4);
        asm volatile("cp.async.cg.shared.global [%0], [%1], 16;\n" :: "r"(sa), "l"(gp));
    }
    asm volatile("cp.async.commit_group;\n");
}

__global__ void __launch_bounds__(NTHR, 1)
lstm_persist_kernel(int layer, const float* __restrict__ h0,
                    const float* __restrict__ c0,
                    const float* __restrict__ Whh_ext)
{
    extern __shared__ float sm[];
    float* W_s = sm;                    // [32][1032] tf32-rounded, k-permuted
    float* A_s = W_s + 32*1032;         // [2][64][APITCH] h chunk double buffer
    float* D_s = A_s + 2*CHF;           // [64][36]
    float* C_s = D_s + 64*36;           // [512] resident cell state

    const int tid  = threadIdx.x;
    const int lane = tid & 31;
    const int warp = tid >> 5;
    const int wm = warp & 3, wn = warp >> 2;   // warp tile m16 x n16
    const int cta = blockIdx.x;
    const int d8  = cta * 8;
    const int m_base = wm*16, n_base = wn*16;

    const float* Whh = layer ? Whh_ext : g_Whh0;
    float* hs = layer ? g_hs1 : g_hs0;
    const float* xg = g_xg;

    unsigned bcnt = g_flags[cta];       // all flags equal at launch entry

    // one-time: load + permute + tf32-round W slice into smem
    for (int idx = tid; idx < 32*1024; idx += NTHR){
        int n = idx >> 10, k = idx & 1023;
        int g = n >> 3, dd = n & 7;
        float v = Whh[(size_t)(g*1024 + d8 + dd)*DIM + k];
        int kp = (k & ~7) + spf(k & 7);
        W_s[n*1032 + kp] = __uint_as_float(f2tf32(v));
    }
    // init cell state + publish permuted h0
    for (int idx = tid; idx < 512; idx += NTHR){
        int b = idx >> 3, dd = idx & 7;
        C_s[idx] = c0[(size_t)layer*B*DIM + b*DIM + d8 + dd];
        float hv = h0[(size_t)layer*B*DIM + b*DIM + d8 + dd];
        g_hex[0][b*DIM + d8 + spf(dd)] = __uint_as_float(f2tf32(hv));
    }
    flag_barrier(++bcnt);

    int p = 0;
    const int j2 = 2*(lane & 3);
    const int arow = lane >> 2;

    for (int t = 0; t < T; t++){
        const float* hsrc = g_hex[p];
        float acc[2][4];
#pragma unroll
        for (int ni = 0; ni < 2; ni++)
#pragma unroll
            for (int q = 0; q < 4; q++) acc[ni][q] = 0.f;

        load_chunk(hsrc, 0, A_s, tid);

        for (int kcc = 0; kcc < 8; kcc++){
            asm volatile("cp.async.wait_group 0;\n");
            __syncthreads();            // chunk kcc visible; buf (kcc+1)&1 free
            if (kcc < 7)
                load_chunk(hsrc, kcc+1, A_s + ((kcc+1)&1)*CHF, tid);
            float* Ab = A_s + (kcc & 1)*CHF;
#pragma unroll
            for (int kk = 0; kk < 16; kk++){
                unsigned a[4], bf[2][2];
                const float* ap = Ab + (m_base + arow)*APITCH + kk*8 + j2;
                float2 v01 = *(const float2*)ap;               // (a0, a2)
                float2 v23 = *(const float2*)(ap + 8*APITCH);  // (a1, a3)
                a[0] = __float_as_uint(v01.x);
                a[2] = __float_as_uint(v01.y);
                a[1] = __float_as_uint(v23.x);
                a[3] = __float_as_uint(v23.y);
#pragma unroll
                for (int ni = 0; ni < 2; ni++){
                    const float* bp = W_s + (n_base + ni*8 + arow)*1032 + kcc*K_CH + kk*8 + j2;
                    float2 bv = *(const float2*)bp;            // (b0, b1)
                    bf[ni][0] = __float_as_uint(bv.x);
                    bf[ni][1] = __float_as_uint(bv.y);
                }
#pragma unroll
                for (int ni = 0; ni < 2; ni++)
                    mma_tf32(acc[ni], a, bf[ni]);
            }
        }

        // dump C fragments to D_s (warps write disjoint m16 x n16 regions)
#pragma unroll
        for (int ni = 0; ni < 2; ni++){
            int r = m_base + arow;
            int ccol = n_base + ni*8 + j2;
            D_s[r*36 + ccol]       = acc[ni][0];
            D_s[r*36 + ccol + 1]   = acc[ni][1];
            D_s[(r+8)*36 + ccol]   = acc[ni][2];
            D_s[(r+8)*36 + ccol+1] = acc[ni][3];
        }
        __syncthreads();

        // activations: 512 (b,dd) cells, 2 per thread
#pragma unroll
        for (int ii = 0; ii < 2; ii++){
            int cell = tid + ii*NTHR;
            int b = cell >> 3, dd = cell & 7;
            size_t xb = ((size_t)(t*64 + b))*G4 + d8 + dd;
            float gi = D_s[b*36 + dd]      + xg[xb];
            float gf = D_s[b*36 + 8 + dd]  + xg[xb + 1024];
            float gc = D_s[b*36 + 16 + dd] + xg[xb + 2048];
            float go = D_s[b*36 + 24 + dd] + xg[xb + 3072];
            float si = 1.f/(1.f + expf(-gi));
            float sf = 1.f/(1.f + expf(-gf));
            float so = 1.f/(1.f + expf(-go));
            float cv = sf*C_s[cell] + si*tanhf(gc);
            float hv = so*tanhf(cv);
            C_s[cell] = cv;
            hs[(size_t)t*B*DIM + b*DIM + d8 + dd] = hv;
            g_hex[p^1][b*DIM + d8 + spf(dd)] = __uint_as_float(f2tf32(hv));
        }
        flag_barrier(++bcnt);
        p ^= 1;
    }

    // final cell state
    for (int idx = tid; idx < 512; idx += NTHR){
        int b = idx >> 3, dd = idx & 7;
        g_cfin[layer][b*DIM + d8 + dd] = C_s[idx];
    }
}

// ---------------- pack new_h / new_c ----------------------------------------
__global__ void finals_kernel(float* __restrict__ out)
{
    int i = blockIdx.x*blockDim.x + threadIdx.x;
    if (i < HC_N) {
        int l = i / (B*DIM);
        int r = i % (B*DIM);
        const float* hsl = l ? g_hs1 : g_hs0;
        out[LOGITS_N + i]        = hsl[(size_t)(T-1)*B*DIM + r];
        out[LOGITS_N + HC_N + i] = g_cfin[l][r];
    }
}

// ---------------- launch -----------------------------------------------------
#define PERSIST_SMEM ((32*1032 + 2*CHF + 64*36 + 512) * 4)

extern "C" void kernel_launch(void* const* d_in, const int* in_sizes, int n_in,
                              void* d_out, int out_size)
{
    const int*   x     = (const int*)  d_in[0];
    const float* h0    = (const float*)d_in[1];
    const float* c0    = (const float*)d_in[2];
    const float* emb   = (const float*)d_in[3];
    const float* v_ih0 = (const float*)d_in[4];
    const float* g_ih0 = (const float*)d_in[5];
    const float* v_hh0 = (const float*)d_in[6];
    const float* g_hh0 = (const float*)d_in[7];
    const float* b_ih0 = (const float*)d_in[8];
    const float* b_hh0 = (const float*)d_in[9];
    const float* W_ih1 = (const float*)d_in[10];
    const float* W_hh1 = (const float*)d_in[11];
    const float* b_ih1 = (const float*)d_in[12];
    const float* b_hh1 = (const float*)d_in[13];
    const float* W_out = (const float*)d_in[14];
    const float* b_out = (const float*)d_in[15];
    float* out = (float*)d_out;

    cudaFuncSetAttribute(lstm_persist_kernel,
                         cudaFuncAttributeMaxDynamicSharedMemorySize, PERSIST_SMEM);

    wnorm_kernel<<<G4, 256>>>(v_ih0, g_ih0, 0);
    wnorm_kernel<<<G4, 256>>>(v_hh0, g_hh0, 1);

    // layer 0 input-side gates
    gemm128_kernel<<<dim3(G4/128, (T*B)/128), 256>>>(
        0, emb, nullptr, nullptr, b_ih0, b_hh0, x, G4, EMB);

    // layer 0 recurrence (persistent)
    lstm_persist_kernel<<<NCTA, NTHR, PERSIST_SMEM>>>(0, h0, c0, nullptr);

    // layer 1 input-side gates
    gemm128_kernel<<<dim3(G4/128, (T*B)/128), 256>>>(
        1, nullptr, W_ih1, nullptr, b_ih1, b_hh1, nullptr, G4, DIM);

    // layer 1 recurrence (persistent)
    lstm_persist_kernel<<<NCTA, NTHR, PERSIST_SMEM>>>(1, h0, c0, W_hh1);

    // logits
    gemm128_kernel<<<dim3(VOCAB/128, (T*B)/128), 256>>>(
        2, nullptr, W_out, out, b_out, nullptr, nullptr, VOCAB, DIM);

    finals_kernel<<<(HC_N + 255)/256, 256>>>(out);
}